// round 11
// baseline (speedup 1.0000x reference)
#include <cuda_runtime.h>
#include <cstdint>
#include <math.h>

#define BB    32
#define LL    512
#define HIDC  512
#define NHH   8
#define EE    64
#define TOPK  62

// ---------------- device scratch (zero-initialized at module load) ----------------
__device__ float g_Q [BB*LL*HIDC];
__device__ float g_K [BB*LL*HIDC];
__device__ float g_V [BB*LL*HIDC];
__device__ float g_qs[BB*LL*HIDC];
__device__ float g_ks[BB*LL*HIDC];
__device__ float g_vs[BB*LL*HIDC];
__device__ float g_ctx[BB*LL*HIDC];
__device__ float g_hb [BB*LL*HIDC];
__device__ float g_G [BB*LL*LL];      // Gram: G[b,l,l'] = sum_c Q[b,l,c]K[b,l',c]
__device__ float g_R [BB*LL];         // diagonal sums of G
__device__ float g_h [LL];            // band filter impulse response (includes 1/L)
__device__ float g_T [LL*LL];         // circulant filter matrix T[t,l]=h[(t-l)&511]
__device__ float g_wk[BB*TOPK];
__device__ int   g_dk[BB*TOPK];

// ---------------- trig/filter tables ----------------
__global__ void init_h() {
    int m = threadIdx.x;
    float acc = 0.f;
    for (int f = 102; f < 256; f++) {
        int ph = (f * m) & (LL - 1);
        acc += 2.0f * cospif((float)ph * (1.0f / 256.0f));
    }
    {   // Nyquist f=256, weight 1
        int ph = (256 * m) & (LL - 1);
        acc += cospif((float)ph * (1.0f / 256.0f));
    }
    g_h[m] = acc * (1.0f / 512.0f);
}

__global__ void init_T() {
    int t = blockIdx.x, l = threadIdx.x;
    g_T[t * LL + l] = g_h[(t - l) & (LL - 1)];
}

// ---------------- tf32 helpers ----------------
__device__ __forceinline__ unsigned int to_tf32(float x) {
    unsigned int u;
    asm("cvt.rna.tf32.f32 %0, %1;" : "=r"(u) : "f"(x));
    return u;
}

__device__ __forceinline__ void mma_tf32(float* d, const uint4& a, const uint2& b) {
    asm volatile(
        "mma.sync.aligned.m16n8k8.row.col.f32.tf32.tf32.f32 "
        "{%0,%1,%2,%3}, {%4,%5,%6,%7}, {%8,%9}, {%0,%1,%2,%3};\n"
        : "+f"(d[0]), "+f"(d[1]), "+f"(d[2]), "+f"(d[3])
        : "r"(a.x), "r"(a.y), "r"(a.z), "r"(a.w), "r"(b.x), "r"(b.y));
}

// ---------------- tf32 tensor-core GEMM body ----------------
// C[128,128] tile: C = A * op(B), A row-major [M,512], all strides 512, K=512.
// BNN=0: C[m,n] = sum_k A[m,k]*B[n,k]  (B row-major [N,512])
// BNN=1: C[m,n] = sum_k A[m,k]*B[k,n]  (B row-major [512,N=512])
// 256 threads = 8 warps (4x2); warp tile 32x64.
// Smem holds fragment-major tiles: one LDS.128 per A-frag, LDS.64 per B-frag.
template<int RES, int BNN, int BIASF>
__device__ __forceinline__ void mma_gemm_body(
    const float* __restrict__ A, const float* __restrict__ B,
    const float* __restrict__ bias, const float* __restrict__ Rres,
    float* __restrict__ C)
{
    __shared__ unsigned int As2[2048];   // [mt(8)][ks(2)][lane(32)][slot(4)]
    __shared__ unsigned int Bs2[2048];   // [nt(16)][ks(2)][lane(32)][slot(2)]
    int tid = threadIdx.x, lane = tid & 31, wid = tid >> 5;
    int wm = wid >> 1, wn = wid & 1;
    int bm = blockIdx.x * 128, bn = blockIdx.y * 128;

    float acc[2][8][4];
    #pragma unroll
    for (int mi = 0; mi < 2; mi++)
        #pragma unroll
        for (int ni = 0; ni < 8; ni++)
            #pragma unroll
            for (int j = 0; j < 4; j++) acc[mi][ni][j] = 0.f;

    for (int k0 = 0; k0 < 512; k0 += 16) {
        // ---- stage A tile 128x16 into fragment layout ----
        #pragma unroll
        for (int q = 0; q < 2; q++) {
            int v = tid + q * 256;
            int r = v >> 2, c0 = (v & 3) * 4;
            float4 av = *(const float4*)&A[(size_t)(bm + r) * 512 + k0 + c0];
            int mt = r >> 4;
            int ks = c0 >> 3;
            int s  = ((r >> 3) & 1) + ((c0 & 4) ? 2 : 0);
            unsigned int* dst = &As2[((((mt*2 + ks)*32) + ((r & 7) << 2)) << 2) + s];
            dst[0]  = to_tf32(av.x);
            dst[4]  = to_tf32(av.y);
            dst[8]  = to_tf32(av.z);
            dst[12] = to_tf32(av.w);
        }
        // ---- stage B tile (128 cols of C) into fragment layout ----
        if (BNN == 0) {
            #pragma unroll
            for (int q = 0; q < 2; q++) {
                int v = tid + q * 256;
                int n = v >> 2, c0 = (v & 3) * 4;
                float4 bv = *(const float4*)&B[(size_t)(bn + n) * 512 + k0 + c0];
                int nt = n >> 3, ks = c0 >> 3;
                int s  = (c0 & 4) ? 1 : 0;
                unsigned int* dst = &Bs2[((((nt*2 + ks)*32) + ((n & 7) << 2)) << 1) + s];
                dst[0] = to_tf32(bv.x);
                dst[2] = to_tf32(bv.y);
                dst[4] = to_tf32(bv.z);
                dst[6] = to_tf32(bv.w);
            }
        } else {
            #pragma unroll
            for (int q = 0; q < 2; q++) {
                int v = tid + q * 256;
                int kr = v >> 5, c0 = (v & 31) * 4;
                float4 bv = *(const float4*)&B[(size_t)(k0 + kr) * 512 + bn + c0];
                int kk = kr & 7, ks = kr >> 3;
                int s  = (kk >> 2) & 1;
                int l0 = ((c0 & 7) << 2) | (kk & 3);
                int nt = c0 >> 3;
                unsigned int* dst = &Bs2[((((nt*2 + ks)*32) + l0) << 1) + s];
                dst[0]  = to_tf32(bv.x);
                dst[8]  = to_tf32(bv.y);
                dst[16] = to_tf32(bv.z);
                dst[24] = to_tf32(bv.w);
            }
        }
        __syncthreads();
        // ---- consume 2 k-steps of 8 ----
        #pragma unroll
        for (int ks = 0; ks < 2; ks++) {
            uint4 af[2];
            uint2 bf[8];
            #pragma unroll
            for (int mi = 0; mi < 2; mi++)
                af[mi] = *(const uint4*)&As2[((((wm*2 + mi)*2 + ks)*32) + lane) << 2];
            #pragma unroll
            for (int ni = 0; ni < 8; ni++)
                bf[ni] = *(const uint2*)&Bs2[((((wn*8 + ni)*2 + ks)*32) + lane) << 1];
            #pragma unroll
            for (int mi = 0; mi < 2; mi++)
                #pragma unroll
                for (int ni = 0; ni < 8; ni++)
                    mma_tf32(acc[mi][ni], af[mi], bf[ni]);
        }
        __syncthreads();
    }

    // ---- epilogue ----
    int r0 = bm + wm*32 + (lane >> 2);
    int cb = bn + wn*64 + 2*(lane & 3);
    #pragma unroll
    for (int mi = 0; mi < 2; mi++) {
        int ra = r0 + mi*16;
        int rb = ra + 8;
        #pragma unroll
        for (int ni = 0; ni < 8; ni++) {
            int col = cb + ni*8;
            float b0 = 0.f, b1 = 0.f;
            if (BIASF) { b0 = bias[col]; b1 = bias[col+1]; }
            float2 va, vb;
            va.x = acc[mi][ni][0] + b0; va.y = acc[mi][ni][1] + b1;
            vb.x = acc[mi][ni][2] + b0; vb.y = acc[mi][ni][3] + b1;
            if (RES) {
                va.x += Rres[(size_t)ra*512 + col];   va.y += Rres[(size_t)ra*512 + col+1];
                vb.x += Rres[(size_t)rb*512 + col];   vb.y += Rres[(size_t)rb*512 + col+1];
            }
            *(float2*)&C[(size_t)ra*512 + col] = va;
            *(float2*)&C[(size_t)rb*512 + col] = vb;
        }
    }
}

// ---------------- GEMM kernel instantiations ----------------
__global__ __launch_bounds__(256)
void qkv_mma(const float* __restrict__ A,
             const float* __restrict__ B0, const float* __restrict__ b0, float* __restrict__ C0,
             const float* __restrict__ B1, const float* __restrict__ b1, float* __restrict__ C1,
             const float* __restrict__ B2, const float* __restrict__ b2, float* __restrict__ C2)
{
    const float* Bw; const float* bias; float* C;
    if (blockIdx.z == 0)      { Bw = B0; bias = b0; C = C0; }
    else if (blockIdx.z == 1) { Bw = B1; bias = b1; C = C1; }
    else                      { Bw = B2; bias = b2; C = C2; }
    mma_gemm_body<0,0,1>(A, Bw, bias, nullptr, C);
}

__global__ __launch_bounds__(256)
void gram_mma()
{
    int b = blockIdx.z;
    mma_gemm_body<0,0,0>(g_Q + (size_t)b*LL*HIDC, g_K + (size_t)b*LL*HIDC,
                         nullptr, nullptr, g_G + (size_t)b*LL*LL);
}

__global__ __launch_bounds__(256)
void circ_mma()
{
    int bz = blockIdx.z;
    int b  = bz & (BB - 1);
    int wsel = bz >> 5;
    const float* X; float* Out;
    if (wsel == 0)      { X = g_Q; Out = g_qs; }
    else if (wsel == 1) { X = g_K; Out = g_ks; }
    else                { X = g_V; Out = g_vs; }
    mma_gemm_body<0,1,0>(g_T, X + (size_t)b*LL*HIDC, nullptr, nullptr,
                         Out + (size_t)b*LL*HIDC);
}

__global__ __launch_bounds__(256)
void outproj_mma(const float* __restrict__ A, const float* __restrict__ Bw,
                 const float* __restrict__ bias, const float* __restrict__ Rres,
                 float* __restrict__ C)
{
    mma_gemm_body<1,0,1>(A, Bw, bias, Rres, C);
}

// ---------------- diagonal sums: R[b,d] = sum_l G[b, l, (l-d)&511] ----------------
// Coalesced: stage 16 G-rows into smem, each thread owns d=tid and d=tid+256.
__global__ __launch_bounds__(256)
void diag_sum()
{
    __shared__ float tile[16*LL];
    int b = blockIdx.x, tid = threadIdx.x;
    const float* Gb = g_G + (size_t)b*LL*LL;
    float r0 = 0.f, r1 = 0.f;
    for (int t0 = 0; t0 < LL; t0 += 16) {
        for (int i = tid; i < 16*LL/4; i += 256) {
            int row = i >> 7, c = (i & 127) * 4;
            *(float4*)&tile[row*LL + c] = *(const float4*)&Gb[(size_t)(t0 + row)*LL + c];
        }
        __syncthreads();
        #pragma unroll
        for (int l = 0; l < 16; l++) {
            int Lr = t0 + l;
            r0 += tile[l*LL + ((Lr - tid) & (LL - 1))];
            r1 += tile[l*LL + ((Lr - tid - 256) & (LL - 1))];
        }
        __syncthreads();
    }
    g_R[b*LL + tid]       = r0;
    g_R[b*LL + tid + 256] = r1;
}

// ---------------- mean-corr via R*h convolution + top-k + softmax (one block/b) -----
__global__ __launch_bounds__(256)
void mc_topk()
{
    int b = blockIdx.x, tid = threadIdx.x;
    __shared__ float Rs[LL], hs[LL];
    __shared__ float mc[LL];
    __shared__ float bv[256]; __shared__ int bi[256];
    __shared__ float wk[TOPK]; __shared__ int dk[TOPK];
    __shared__ float ev[TOPK]; __shared__ float ssum;

    for (int i = tid; i < LL; i += 256) { Rs[i] = g_R[b*LL + i]; hs[i] = g_h[i]; }
    __syncthreads();

    const float sc = 1.0f / 512.0f;   // 1/(H*E) mean over channels
    for (int t = tid; t < LL; t += 256) {
        float acc = 0.f;
        for (int d = 0; d < LL; d++)
            acc += Rs[d] * hs[(t - d) & (LL - 1)];
        mc[t] = acc * sc;
    }
    __syncthreads();

    for (int k = 0; k < TOPK; k++) {
        float v1 = mc[tid], v2 = mc[tid + 256];
        float vv; int ii;
        if (v2 > v1) { vv = v2; ii = tid + 256; } else { vv = v1; ii = tid; }
        bv[tid] = vv; bi[tid] = ii;
        __syncthreads();
        for (int s = 128; s > 0; s >>= 1) {
            if (tid < s) {
                float ov = bv[tid + s]; int oi = bi[tid + s];
                if (ov > bv[tid] || (ov == bv[tid] && oi < bi[tid])) { bv[tid] = ov; bi[tid] = oi; }
            }
            __syncthreads();
        }
        if (tid == 0) { wk[k] = bv[0]; dk[k] = bi[0]; mc[bi[0]] = -INFINITY; }
        __syncthreads();
    }
    if (tid < TOPK) ev[tid] = expf(wk[tid] - wk[0]);
    __syncthreads();
    if (tid == 0) { float s = 0.f; for (int k = 0; k < TOPK; k++) s += ev[k]; ssum = s; }
    __syncthreads();
    if (tid < TOPK) { g_wk[b*TOPK + tid] = ev[tid] / ssum; g_dk[b*TOPK + tid] = dk[tid]; }
}

// ---------------- flash attention (fp32) per (b,h), writes 0.5*ctx_sp ----------------
__global__ __launch_bounds__(256)
void attn_kernel(const float* __restrict__ mask)
{
    extern __shared__ float smdyn[];
    float* Qs = smdyn;
    float* Ks = Qs + 64*65;
    float* Vs = Ks + 64*65;
    float* Ps = Vs + 64*65;
    __shared__ float rm[64], rl[64], rf[64];
    int bh = blockIdx.z, b = bh >> 3, h = bh & 7;
    int l0 = blockIdx.x * 64;
    int tid = threadIdx.x, tx = tid & 15, ty = tid >> 4;

    for (int v = tid; v < 64*16; v += 256) {
        int r = v >> 4, c4 = (v & 15) * 4;
        float4 qv = *(const float4*)&g_qs[((size_t)b*LL + l0 + r)*HIDC + h*EE + c4];
        Qs[r*65+c4+0]=qv.x; Qs[r*65+c4+1]=qv.y; Qs[r*65+c4+2]=qv.z; Qs[r*65+c4+3]=qv.w;
    }
    if (tid < 64) { rm[tid] = -INFINITY; rl[tid] = 0.f; }
    float acc[4][4] = {};
    __syncthreads();

    for (int m0 = 0; m0 < LL; m0 += 64) {
        for (int v = tid; v < 64*16; v += 256) {
            int r = v >> 4, c4 = (v & 15) * 4;
            size_t base = ((size_t)b*LL + m0 + r)*HIDC + h*EE + c4;
            float4 kv = *(const float4*)&g_ks[base];
            float4 vv = *(const float4*)&g_vs[base];
            Ks[r*65+c4+0]=kv.x; Ks[r*65+c4+1]=kv.y; Ks[r*65+c4+2]=kv.z; Ks[r*65+c4+3]=kv.w;
            Vs[r*65+c4+0]=vv.x; Vs[r*65+c4+1]=vv.y; Vs[r*65+c4+2]=vv.z; Vs[r*65+c4+3]=vv.w;
        }
        __syncthreads();

        float s[4][4] = {};
        #pragma unroll 8
        for (int e = 0; e < 64; e++) {
            float qa[4], kb[4];
            #pragma unroll
            for (int i = 0; i < 4; i++) qa[i] = Qs[(ty*4+i)*65 + e];
            #pragma unroll
            for (int j = 0; j < 4; j++) kb[j] = Ks[(tx*4+j)*65 + e];
            #pragma unroll
            for (int i = 0; i < 4; i++)
                #pragma unroll
                for (int j = 0; j < 4; j++)
                    s[i][j] += qa[i]*kb[j];
        }
        #pragma unroll
        for (int i = 0; i < 4; i++)
            #pragma unroll
            for (int j = 0; j < 4; j++)
                s[i][j] = s[i][j]*0.125f +
                    mask[((size_t)b*LL + l0 + ty*4 + i)*LL + m0 + tx*4 + j];

        float tm[4];
        #pragma unroll
        for (int i = 0; i < 4; i++)
            tm[i] = fmaxf(fmaxf(s[i][0], s[i][1]), fmaxf(s[i][2], s[i][3]));
        #pragma unroll
        for (int o = 1; o < 16; o <<= 1)
            #pragma unroll
            for (int i = 0; i < 4; i++)
                tm[i] = fmaxf(tm[i], __shfl_xor_sync(0xffffffffu, tm[i], o));
        if (tx == 0) {
            #pragma unroll
            for (int i = 0; i < 4; i++) {
                int r = ty*4 + i;
                float mo = rm[r];
                float mn = fmaxf(mo, tm[i]);
                rf[r] = expf(mo - mn);
                rm[r] = mn;
            }
        }
        __syncthreads();

        float ts[4] = {0.f, 0.f, 0.f, 0.f};
        #pragma unroll
        for (int i = 0; i < 4; i++) {
            float mrow = rm[ty*4 + i];
            #pragma unroll
            for (int j = 0; j < 4; j++) {
                float p = expf(s[i][j] - mrow);
                ts[i] += p;
                Ps[(ty*4+i)*65 + tx*4 + j] = p;
            }
        }
        #pragma unroll
        for (int o = 1; o < 16; o <<= 1)
            #pragma unroll
            for (int i = 0; i < 4; i++)
                ts[i] += __shfl_xor_sync(0xffffffffu, ts[i], o);
        if (tx == 0) {
            #pragma unroll
            for (int i = 0; i < 4; i++) {
                int r = ty*4 + i;
                rl[r] = rl[r]*rf[r] + ts[i];
            }
        }
        __syncthreads();

        #pragma unroll
        for (int i = 0; i < 4; i++) {
            float f = rf[ty*4 + i];
            #pragma unroll
            for (int j = 0; j < 4; j++) acc[i][j] *= f;
        }
        #pragma unroll 8
        for (int c = 0; c < 64; c++) {
            float pv[4], vv[4];
            #pragma unroll
            for (int i = 0; i < 4; i++) pv[i] = Ps[(ty*4+i)*65 + c];
            #pragma unroll
            for (int j = 0; j < 4; j++) vv[j] = Vs[c*65 + tx*4 + j];
            #pragma unroll
            for (int i = 0; i < 4; i++)
                #pragma unroll
                for (int j = 0; j < 4; j++)
                    acc[i][j] += pv[i]*vv[j];
        }
        __syncthreads();
    }

    #pragma unroll
    for (int i = 0; i < 4; i++) {
        float inv = 1.0f / rl[ty*4 + i];
        #pragma unroll
        for (int j = 0; j < 4; j++)
            g_ctx[((size_t)b*LL + l0 + ty*4 + i)*HIDC + h*EE + tx*4 + j] =
                0.5f * acc[i][j] * inv;
    }
}

// ---------------- time-delay aggregation: ctx += 0.5 * sum_k w_k * V[(l+d_k)%L] ------
__global__ __launch_bounds__(256)
void delay_agg()
{
    __shared__ float ws[TOPK]; __shared__ int ds[TOPK];
    int l0 = blockIdx.x * 8, b = blockIdx.y, tid = threadIdx.x;
    if (tid < TOPK) { ws[tid] = g_wk[b*TOPK + tid]; ds[tid] = g_dk[b*TOPK + tid]; }
    __syncthreads();
    int c2 = tid;  // float2 index: 256 threads cover 512 floats
    const float2* Vb = (const float2*)(g_V + (size_t)b*LL*HIDC);
    float2 acc[8];
    #pragma unroll
    for (int i = 0; i < 8; i++) acc[i] = make_float2(0.f, 0.f);
    for (int k = 0; k < TOPK; k++) {
        float w = ws[k]; int d = ds[k];
        #pragma unroll
        for (int i = 0; i < 8; i++) {
            int pos = (l0 + i + d) & (LL - 1);
            float2 v = Vb[(size_t)pos*(HIDC/2) + c2];
            acc[i].x += w*v.x; acc[i].y += w*v.y;
        }
    }
    #pragma unroll
    for (int i = 0; i < 8; i++) {
        size_t off = ((size_t)b*LL + l0 + i)*(HIDC/2) + c2;
        float2* C = (float2*)g_ctx;
        float2 cur = C[off];
        cur.x += 0.5f*acc[i].x; cur.y += 0.5f*acc[i].y;
        C[off] = cur;
    }
}

// ---------------- layernorm ----------------
__global__ __launch_bounds__(128)
void ln_kernel(const float* __restrict__ hb, const float* __restrict__ w,
               const float* __restrict__ bp, float* __restrict__ out)
{
    int row = blockIdx.x, tid = threadIdx.x;
    const float* hr = hb + (size_t)row*HIDC;
    float4 xv = *(const float4*)&hr[tid*4];
    float s  = xv.x + xv.y + xv.z + xv.w;
    float ss = xv.x*xv.x + xv.y*xv.y + xv.z*xv.z + xv.w*xv.w;
    #pragma unroll
    for (int o = 16; o; o >>= 1) {
        s  += __shfl_xor_sync(0xffffffffu, s,  o);
        ss += __shfl_xor_sync(0xffffffffu, ss, o);
    }
    __shared__ float s1[4], s2s[4];
    int wp = tid >> 5;
    if ((tid & 31) == 0) { s1[wp] = s; s2s[wp] = ss; }
    __syncthreads();
    float st  = s1[0] + s1[1] + s1[2] + s1[3];
    float sst = s2s[0] + s2s[1] + s2s[2] + s2s[3];
    float mean = st * (1.0f / HIDC);
    float var  = fmaxf(sst * (1.0f / HIDC) - mean*mean, 0.0f);
    float inv  = rsqrtf(var + 1e-12f);
    int c = tid * 4;
    float4 o4;
    o4.x = w[c+0]*((xv.x - mean)*inv) + bp[c+0];
    o4.y = w[c+1]*((xv.y - mean)*inv) + bp[c+1];
    o4.z = w[c+2]*((xv.z - mean)*inv) + bp[c+2];
    o4.w = w[c+3]*((xv.w - mean)*inv) + bp[c+3];
    *(float4*)&out[(size_t)row*HIDC + c] = o4;
}

// ---------------- launch ----------------
extern "C" void kernel_launch(void* const* d_in, const int* in_sizes, int n_in,
                              void* d_out, int out_size)
{
    const float* x    = (const float*)d_in[0];
    const float* mask = (const float*)d_in[1];
    const float* Wq = (const float*)d_in[2];
    const float* bq = (const float*)d_in[3];
    const float* Wk = (const float*)d_in[4];
    const float* bk = (const float*)d_in[5];
    const float* Wv = (const float*)d_in[6];
    const float* bv = (const float*)d_in[7];
    const float* Wd = (const float*)d_in[8];
    const float* bd = (const float*)d_in[9];
    const float* lw = (const float*)d_in[10];
    const float* lb = (const float*)d_in[11];
    float* out = (float*)d_out;

    float *pQ,*pK,*pV,*pctx,*ph;
    cudaGetSymbolAddress((void**)&pQ,  g_Q);
    cudaGetSymbolAddress((void**)&pK,  g_K);
    cudaGetSymbolAddress((void**)&pV,  g_V);
    cudaGetSymbolAddress((void**)&pctx,g_ctx);
    cudaGetSymbolAddress((void**)&ph,  g_hb);

    const int M = BB * LL;   // 16384

    init_h<<<1, LL>>>();
    init_T<<<LL, LL>>>();

    // fused QKV via tf32 tensor cores: z selects weight set
    qkv_mma<<<dim3(M/128, HIDC/128, 3), 256>>>(x, Wq, bq, pQ, Wk, bk, pK, Wv, bv, pV);

    // Gram matrices + diagonal sums -> R -> topk weights
    gram_mma<<<dim3(LL/128, LL/128, BB), 256>>>();
    diag_sum<<<BB, 256>>>();
    mc_topk<<<BB, 256>>>();

    // band filter via circulant GEMM (NN) for qs,ks,vs
    circ_mma<<<dim3(LL/128, HIDC/128, 3*BB), 256>>>();

    cudaFuncSetAttribute(attn_kernel, cudaFuncAttributeMaxDynamicSharedMemorySize,
                         4*64*65*sizeof(float));
    attn_kernel<<<dim3(LL/64, 1, BB*NHH), 256, 4*64*65*sizeof(float)>>>(mask);

    delay_agg<<<dim3(LL/8, BB), 256>>>();

    // output projection + residual via tf32 tensor cores
    outproj_mma<<<dim3(M/128, HIDC/128, 1), 256>>>(pctx, Wd, bd, x, ph);

    ln_kernel<<<M, 128>>>(ph, lw, lb, out);
}

// round 13
// speedup vs baseline: 1.5182x; 1.5182x over previous
#include <cuda_runtime.h>
#include <cstdint>
#include <math.h>

#define BB    32
#define LL    512
#define HIDC  512
#define NHH   8
#define EE    64
#define TOPK  62

// ---------------- device scratch (zero-initialized at module load) ----------------
__device__ float g_Q [BB*LL*HIDC];
__device__ float g_K [BB*LL*HIDC];
__device__ float g_V [BB*LL*HIDC];
__device__ float g_qs[BB*LL*HIDC];
__device__ float g_ks[BB*LL*HIDC];
__device__ float g_vs[BB*LL*HIDC];
__device__ float g_ctx[BB*LL*HIDC];
__device__ float g_hb [BB*LL*HIDC];
__device__ float g_G [BB*LL*LL];      // Gram: G[b,l,l'] = sum_c Q[b,l,c]K[b,l',c]
__device__ float g_R [BB*LL];         // diagonal sums of G
__device__ float g_h [LL];            // band filter impulse response (includes 1/L)
__device__ float g_T [LL*LL];         // circulant filter matrix T[t,l]=h[(t-l)&511]
__device__ float g_wk[BB*TOPK];
__device__ int   g_dk[BB*TOPK];

// ---------------- trig/filter tables ----------------
__global__ void init_h() {
    int m = threadIdx.x;
    float acc = 0.f;
    for (int f = 102; f < 256; f++) {
        int ph = (f * m) & (LL - 1);
        acc += 2.0f * cospif((float)ph * (1.0f / 256.0f));
    }
    {   // Nyquist f=256, weight 1
        int ph = (256 * m) & (LL - 1);
        acc += cospif((float)ph * (1.0f / 256.0f));
    }
    g_h[m] = acc * (1.0f / 512.0f);
}

__global__ void init_T() {
    int t = blockIdx.x, l = threadIdx.x;
    g_T[t * LL + l] = g_h[(t - l) & (LL - 1)];
}

// ---------------- tf32 helpers ----------------
__device__ __forceinline__ unsigned int to_tf32(float x) {
    unsigned int u;
    asm("cvt.rna.tf32.f32 %0, %1;" : "=r"(u) : "f"(x));
    return u;
}

__device__ __forceinline__ void mma_tf32(float* d, const uint4& a, const uint2& b) {
    asm volatile(
        "mma.sync.aligned.m16n8k8.row.col.f32.tf32.tf32.f32 "
        "{%0,%1,%2,%3}, {%4,%5,%6,%7}, {%8,%9}, {%0,%1,%2,%3};\n"
        : "+f"(d[0]), "+f"(d[1]), "+f"(d[2]), "+f"(d[3])
        : "r"(a.x), "r"(a.y), "r"(a.z), "r"(a.w), "r"(b.x), "r"(b.y));
}

// ---------------- tf32 tensor-core GEMM body (R10 winner: 128x64 tile) ----------------
// C[128,64] tile: C = A * op(B), A row-major [M,512], all strides 512, K=512.
// BNN=0: C[m,n] = sum_k A[m,k]*B[n,k]  (B row-major [N,512])
// BNN=1: C[m,n] = sum_k A[m,k]*B[k,n]  (B row-major [512,N=512])
// 256 threads = 8 warps (4x2), warp tile 32x32.
template<int RES, int BNN, int BIASF>
__device__ __forceinline__ void mma_gemm_body(
    const float* __restrict__ A, const float* __restrict__ B,
    const float* __restrict__ bias, const float* __restrict__ Rres,
    float* __restrict__ C)
{
    __shared__ unsigned int As2[2048];   // [mt(8)][ks(2)][lane(32)][slot(4)]
    __shared__ unsigned int Bs2[1024];   // [nt(8)][ks(2)][lane(32)][slot(2)]
    int tid = threadIdx.x, lane = tid & 31, wid = tid >> 5;
    int wm = wid >> 1, wn = wid & 1;
    int bm = blockIdx.x * 128, bn = blockIdx.y * 64;

    float acc[2][4][4];
    #pragma unroll
    for (int mi = 0; mi < 2; mi++)
        #pragma unroll
        for (int ni = 0; ni < 4; ni++)
            #pragma unroll
            for (int j = 0; j < 4; j++) acc[mi][ni][j] = 0.f;

    for (int k0 = 0; k0 < 512; k0 += 16) {
        // ---- stage A tile 128x16 into fragment layout ----
        #pragma unroll
        for (int q = 0; q < 2; q++) {
            int v = tid + q * 256;
            int r = v >> 2, c0 = (v & 3) * 4;
            float4 av = *(const float4*)&A[(size_t)(bm + r) * 512 + k0 + c0];
            int mt = r >> 4;
            int ks = c0 >> 3;
            int s  = ((r >> 3) & 1) + ((c0 & 4) ? 2 : 0);
            unsigned int* dst = &As2[((((mt*2 + ks)*32) + ((r & 7) << 2)) << 2) + s];
            dst[0]  = to_tf32(av.x);
            dst[4]  = to_tf32(av.y);
            dst[8]  = to_tf32(av.z);
            dst[12] = to_tf32(av.w);
        }
        // ---- stage B tile into fragment layout ----
        if (BNN == 0) {
            int v = tid;
            int n = v >> 2, c0 = (v & 3) * 4;
            float4 bv = *(const float4*)&B[(size_t)(bn + n) * 512 + k0 + c0];
            int nt = n >> 3, ks = c0 >> 3;
            int s  = (c0 & 4) ? 1 : 0;
            unsigned int* dst = &Bs2[((((nt*2 + ks)*32) + ((n & 7) << 2)) << 1) + s];
            dst[0] = to_tf32(bv.x);
            dst[2] = to_tf32(bv.y);
            dst[4] = to_tf32(bv.z);
            dst[6] = to_tf32(bv.w);
        } else {
            int v = tid;
            int kr = v >> 4, c0 = (v & 15) * 4;
            float4 bv = *(const float4*)&B[(size_t)(k0 + kr) * 512 + bn + c0];
            int kk = kr & 7, ks = kr >> 3;
            int s  = (kk >> 2) & 1;
            int l0 = ((c0 & 7) << 2) | (kk & 3);
            int nt = c0 >> 3;
            unsigned int* dst = &Bs2[((((nt*2 + ks)*32) + l0) << 1) + s];
            dst[0]  = to_tf32(bv.x);
            dst[8]  = to_tf32(bv.y);
            dst[16] = to_tf32(bv.z);
            dst[24] = to_tf32(bv.w);
        }
        __syncthreads();
        // ---- consume 2 k-steps of 8 ----
        #pragma unroll
        for (int ks = 0; ks < 2; ks++) {
            uint4 af[2];
            uint2 bf[4];
            #pragma unroll
            for (int mi = 0; mi < 2; mi++)
                af[mi] = *(const uint4*)&As2[((((wm*2 + mi)*2 + ks)*32) + lane) << 2];
            #pragma unroll
            for (int ni = 0; ni < 4; ni++)
                bf[ni] = *(const uint2*)&Bs2[((((wn*4 + ni)*2 + ks)*32) + lane) << 1];
            #pragma unroll
            for (int mi = 0; mi < 2; mi++)
                #pragma unroll
                for (int ni = 0; ni < 4; ni++)
                    mma_tf32(acc[mi][ni], af[mi], bf[ni]);
        }
        __syncthreads();
    }

    // ---- epilogue ----
    int r0 = bm + wm*32 + (lane >> 2);
    int cb = bn + wn*32 + 2*(lane & 3);
    #pragma unroll
    for (int mi = 0; mi < 2; mi++) {
        int ra = r0 + mi*16;
        int rb = ra + 8;
        #pragma unroll
        for (int ni = 0; ni < 4; ni++) {
            int col = cb + ni*8;
            float b0 = 0.f, b1 = 0.f;
            if (BIASF) { b0 = bias[col]; b1 = bias[col+1]; }
            float2 va, vb;
            va.x = acc[mi][ni][0] + b0; va.y = acc[mi][ni][1] + b1;
            vb.x = acc[mi][ni][2] + b0; vb.y = acc[mi][ni][3] + b1;
            if (RES) {
                va.x += Rres[(size_t)ra*512 + col];   va.y += Rres[(size_t)ra*512 + col+1];
                vb.x += Rres[(size_t)rb*512 + col];   vb.y += Rres[(size_t)rb*512 + col+1];
            }
            *(float2*)&C[(size_t)ra*512 + col] = va;
            *(float2*)&C[(size_t)rb*512 + col] = vb;
        }
    }
}

// ---------------- GEMM kernel instantiations ----------------
__global__ __launch_bounds__(256)
void qkv_mma(const float* __restrict__ A,
             const float* __restrict__ B0, const float* __restrict__ b0, float* __restrict__ C0,
             const float* __restrict__ B1, const float* __restrict__ b1, float* __restrict__ C1,
             const float* __restrict__ B2, const float* __restrict__ b2, float* __restrict__ C2)
{
    const float* Bw; const float* bias; float* C;
    if (blockIdx.z == 0)      { Bw = B0; bias = b0; C = C0; }
    else if (blockIdx.z == 1) { Bw = B1; bias = b1; C = C1; }
    else                      { Bw = B2; bias = b2; C = C2; }
    mma_gemm_body<0,0,1>(A, Bw, bias, nullptr, C);
}

__global__ __launch_bounds__(256)
void gram_mma()
{
    int b = blockIdx.z;
    mma_gemm_body<0,0,0>(g_Q + (size_t)b*LL*HIDC, g_K + (size_t)b*LL*HIDC,
                         nullptr, nullptr, g_G + (size_t)b*LL*LL);
}

__global__ __launch_bounds__(256)
void circ_mma()
{
    int bz = blockIdx.z;
    int b  = bz & (BB - 1);
    int wsel = bz >> 5;
    const float* X; float* Out;
    if (wsel == 0)      { X = g_Q; Out = g_qs; }
    else if (wsel == 1) { X = g_K; Out = g_ks; }
    else                { X = g_V; Out = g_vs; }
    mma_gemm_body<0,1,0>(g_T, X + (size_t)b*LL*HIDC, nullptr, nullptr,
                         Out + (size_t)b*LL*HIDC);
}

__global__ __launch_bounds__(256)
void outproj_mma(const float* __restrict__ A, const float* __restrict__ Bw,
                 const float* __restrict__ bias, const float* __restrict__ Rres,
                 float* __restrict__ C)
{
    mma_gemm_body<1,0,1>(A, Bw, bias, Rres, C);
}

// ---------------- diagonal sums: R[b,d] = sum_l G[b, l, (l-d)&511] ----------------
// Coalesced: stage 16 G-rows into smem, each thread owns d=tid and d=tid+256.
__global__ __launch_bounds__(256)
void diag_sum()
{
    __shared__ float tile[16*LL];
    int b = blockIdx.x, tid = threadIdx.x;
    const float* Gb = g_G + (size_t)b*LL*LL;
    float r0 = 0.f, r1 = 0.f;
    for (int t0 = 0; t0 < LL; t0 += 16) {
        for (int i = tid; i < 16*LL/4; i += 256) {
            int row = i >> 7, c = (i & 127) * 4;
            *(float4*)&tile[row*LL + c] = *(const float4*)&Gb[(size_t)(t0 + row)*LL + c];
        }
        __syncthreads();
        #pragma unroll
        for (int l = 0; l < 16; l++) {
            int Lr = t0 + l;
            r0 += tile[l*LL + ((Lr - tid) & (LL - 1))];
            r1 += tile[l*LL + ((Lr - tid - 256) & (LL - 1))];
        }
        __syncthreads();
    }
    g_R[b*LL + tid]       = r0;
    g_R[b*LL + tid + 256] = r1;
}

// ---------------- mean-corr via R*h convolution + top-k + softmax (one block/b) -----
__global__ __launch_bounds__(256)
void mc_topk()
{
    int b = blockIdx.x, tid = threadIdx.x;
    __shared__ float Rs[LL], hs[LL];
    __shared__ float mc[LL];
    __shared__ float bv[256]; __shared__ int bi[256];
    __shared__ float wk[TOPK]; __shared__ int dk[TOPK];
    __shared__ float ev[TOPK]; __shared__ float ssum;

    for (int i = tid; i < LL; i += 256) { Rs[i] = g_R[b*LL + i]; hs[i] = g_h[i]; }
    __syncthreads();

    const float sc = 1.0f / 512.0f;   // 1/(H*E) mean over channels
    for (int t = tid; t < LL; t += 256) {
        float acc = 0.f;
        for (int d = 0; d < LL; d++)
            acc += Rs[d] * hs[(t - d) & (LL - 1)];
        mc[t] = acc * sc;
    }
    __syncthreads();

    for (int k = 0; k < TOPK; k++) {
        float v1 = mc[tid], v2 = mc[tid + 256];
        float vv; int ii;
        if (v2 > v1) { vv = v2; ii = tid + 256; } else { vv = v1; ii = tid; }
        bv[tid] = vv; bi[tid] = ii;
        __syncthreads();
        for (int s = 128; s > 0; s >>= 1) {
            if (tid < s) {
                float ov = bv[tid + s]; int oi = bi[tid + s];
                if (ov > bv[tid] || (ov == bv[tid] && oi < bi[tid])) { bv[tid] = ov; bi[tid] = oi; }
            }
            __syncthreads();
        }
        if (tid == 0) { wk[k] = bv[0]; dk[k] = bi[0]; mc[bi[0]] = -INFINITY; }
        __syncthreads();
    }
    if (tid < TOPK) ev[tid] = expf(wk[tid] - wk[0]);
    __syncthreads();
    if (tid == 0) { float s = 0.f; for (int k = 0; k < TOPK; k++) s += ev[k]; ssum = s; }
    __syncthreads();
    if (tid < TOPK) { g_wk[b*TOPK + tid] = ev[tid] / ssum; g_dk[b*TOPK + tid] = dk[tid]; }
}

// ---------------- flash attention (fp32) per (b,h), writes 0.5*ctx_sp ----------------
__global__ __launch_bounds__(256)
void attn_kernel(const float* __restrict__ mask)
{
    extern __shared__ float smdyn[];
    float* Qs = smdyn;
    float* Ks = Qs + 64*65;
    float* Vs = Ks + 64*65;
    float* Ps = Vs + 64*65;
    __shared__ float rm[64], rl[64], rf[64];
    int bh = blockIdx.z, b = bh >> 3, h = bh & 7;
    int l0 = blockIdx.x * 64;
    int tid = threadIdx.x, tx = tid & 15, ty = tid >> 4;

    for (int v = tid; v < 64*16; v += 256) {
        int r = v >> 4, c4 = (v & 15) * 4;
        float4 qv = *(const float4*)&g_qs[((size_t)b*LL + l0 + r)*HIDC + h*EE + c4];
        Qs[r*65+c4+0]=qv.x; Qs[r*65+c4+1]=qv.y; Qs[r*65+c4+2]=qv.z; Qs[r*65+c4+3]=qv.w;
    }
    if (tid < 64) { rm[tid] = -INFINITY; rl[tid] = 0.f; }
    float acc[4][4] = {};
    __syncthreads();

    for (int m0 = 0; m0 < LL; m0 += 64) {
        for (int v = tid; v < 64*16; v += 256) {
            int r = v >> 4, c4 = (v & 15) * 4;
            size_t base = ((size_t)b*LL + m0 + r)*HIDC + h*EE + c4;
            float4 kv = *(const float4*)&g_ks[base];
            float4 vv = *(const float4*)&g_vs[base];
            Ks[r*65+c4+0]=kv.x; Ks[r*65+c4+1]=kv.y; Ks[r*65+c4+2]=kv.z; Ks[r*65+c4+3]=kv.w;
            Vs[r*65+c4+0]=vv.x; Vs[r*65+c4+1]=vv.y; Vs[r*65+c4+2]=vv.z; Vs[r*65+c4+3]=vv.w;
        }
        __syncthreads();

        float s[4][4] = {};
        #pragma unroll 8
        for (int e = 0; e < 64; e++) {
            float qa[4], kb[4];
            #pragma unroll
            for (int i = 0; i < 4; i++) qa[i] = Qs[(ty*4+i)*65 + e];
            #pragma unroll
            for (int j = 0; j < 4; j++) kb[j] = Ks[(tx*4+j)*65 + e];
            #pragma unroll
            for (int i = 0; i < 4; i++)
                #pragma unroll
                for (int j = 0; j < 4; j++)
                    s[i][j] += qa[i]*kb[j];
        }
        #pragma unroll
        for (int i = 0; i < 4; i++)
            #pragma unroll
            for (int j = 0; j < 4; j++)
                s[i][j] = s[i][j]*0.125f +
                    mask[((size_t)b*LL + l0 + ty*4 + i)*LL + m0 + tx*4 + j];

        float tm[4];
        #pragma unroll
        for (int i = 0; i < 4; i++)
            tm[i] = fmaxf(fmaxf(s[i][0], s[i][1]), fmaxf(s[i][2], s[i][3]));
        #pragma unroll
        for (int o = 1; o < 16; o <<= 1)
            #pragma unroll
            for (int i = 0; i < 4; i++)
                tm[i] = fmaxf(tm[i], __shfl_xor_sync(0xffffffffu, tm[i], o));
        if (tx == 0) {
            #pragma unroll
            for (int i = 0; i < 4; i++) {
                int r = ty*4 + i;
                float mo = rm[r];
                float mn = fmaxf(mo, tm[i]);
                rf[r] = expf(mo - mn);
                rm[r] = mn;
            }
        }
        __syncthreads();

        float ts[4] = {0.f, 0.f, 0.f, 0.f};
        #pragma unroll
        for (int i = 0; i < 4; i++) {
            float mrow = rm[ty*4 + i];
            #pragma unroll
            for (int j = 0; j < 4; j++) {
                float p = expf(s[i][j] - mrow);
                ts[i] += p;
                Ps[(ty*4+i)*65 + tx*4 + j] = p;
            }
        }
        #pragma unroll
        for (int o = 1; o < 16; o <<= 1)
            #pragma unroll
            for (int i = 0; i < 4; i++)
                ts[i] += __shfl_xor_sync(0xffffffffu, ts[i], o);
        if (tx == 0) {
            #pragma unroll
            for (int i = 0; i < 4; i++) {
                int r = ty*4 + i;
                rl[r] = rl[r]*rf[r] + ts[i];
            }
        }
        __syncthreads();

        #pragma unroll
        for (int i = 0; i < 4; i++) {
            float f = rf[ty*4 + i];
            #pragma unroll
            for (int j = 0; j < 4; j++) acc[i][j] *= f;
        }
        #pragma unroll 8
        for (int c = 0; c < 64; c++) {
            float pv[4], vv[4];
            #pragma unroll
            for (int i = 0; i < 4; i++) pv[i] = Ps[(ty*4+i)*65 + c];
            #pragma unroll
            for (int j = 0; j < 4; j++) vv[j] = Vs[c*65 + tx*4 + j];
            #pragma unroll
            for (int i = 0; i < 4; i++)
                #pragma unroll
                for (int j = 0; j < 4; j++)
                    acc[i][j] += pv[i]*vv[j];
        }
        __syncthreads();
    }

    #pragma unroll
    for (int i = 0; i < 4; i++) {
        float inv = 1.0f / rl[ty*4 + i];
        #pragma unroll
        for (int j = 0; j < 4; j++)
            g_ctx[((size_t)b*LL + l0 + ty*4 + i)*HIDC + h*EE + tx*4 + j] =
                0.5f * acc[i][j] * inv;
    }
}

// ---------------- time-delay aggregation: ctx += 0.5 * sum_k w_k * V[(l+d_k)%L] ------
__global__ __launch_bounds__(256)
void delay_agg()
{
    __shared__ float ws[TOPK]; __shared__ int ds[TOPK];
    int l0 = blockIdx.x * 8, b = blockIdx.y, tid = threadIdx.x;
    if (tid < TOPK) { ws[tid] = g_wk[b*TOPK + tid]; ds[tid] = g_dk[b*TOPK + tid]; }
    __syncthreads();
    int c2 = tid;  // float2 index: 256 threads cover 512 floats
    const float2* Vb = (const float2*)(g_V + (size_t)b*LL*HIDC);
    float2 acc[8];
    #pragma unroll
    for (int i = 0; i < 8; i++) acc[i] = make_float2(0.f, 0.f);
    for (int k = 0; k < TOPK; k++) {
        float w = ws[k]; int d = ds[k];
        #pragma unroll
        for (int i = 0; i < 8; i++) {
            int pos = (l0 + i + d) & (LL - 1);
            float2 v = Vb[(size_t)pos*(HIDC/2) + c2];
            acc[i].x += w*v.x; acc[i].y += w*v.y;
        }
    }
    #pragma unroll
    for (int i = 0; i < 8; i++) {
        size_t off = ((size_t)b*LL + l0 + i)*(HIDC/2) + c2;
        float2* C = (float2*)g_ctx;
        float2 cur = C[off];
        cur.x += 0.5f*acc[i].x; cur.y += 0.5f*acc[i].y;
        C[off] = cur;
    }
}

// ---------------- layernorm ----------------
__global__ __launch_bounds__(128)
void ln_kernel(const float* __restrict__ hb, const float* __restrict__ w,
               const float* __restrict__ bp, float* __restrict__ out)
{
    int row = blockIdx.x, tid = threadIdx.x;
    const float* hr = hb + (size_t)row*HIDC;
    float4 xv = *(const float4*)&hr[tid*4];
    float s  = xv.x + xv.y + xv.z + xv.w;
    float ss = xv.x*xv.x + xv.y*xv.y + xv.z*xv.z + xv.w*xv.w;
    #pragma unroll
    for (int o = 16; o; o >>= 1) {
        s  += __shfl_xor_sync(0xffffffffu, s,  o);
        ss += __shfl_xor_sync(0xffffffffu, ss, o);
    }
    __shared__ float s1[4], s2s[4];
    int wp = tid >> 5;
    if ((tid & 31) == 0) { s1[wp] = s; s2s[wp] = ss; }
    __syncthreads();
    float st  = s1[0] + s1[1] + s1[2] + s1[3];
    float sst = s2s[0] + s2s[1] + s2s[2] + s2s[3];
    float mean = st * (1.0f / HIDC);
    float var  = fmaxf(sst * (1.0f / HIDC) - mean*mean, 0.0f);
    float inv  = rsqrtf(var + 1e-12f);
    int c = tid * 4;
    float4 o4;
    o4.x = w[c+0]*((xv.x - mean)*inv) + bp[c+0];
    o4.y = w[c+1]*((xv.y - mean)*inv) + bp[c+1];
    o4.z = w[c+2]*((xv.z - mean)*inv) + bp[c+2];
    o4.w = w[c+3]*((xv.w - mean)*inv) + bp[c+3];
    *(float4*)&out[(size_t)row*HIDC + c] = o4;
}

// ---------------- launch ----------------
extern "C" void kernel_launch(void* const* d_in, const int* in_sizes, int n_in,
                              void* d_out, int out_size)
{
    const float* x    = (const float*)d_in[0];
    const float* mask = (const float*)d_in[1];
    const float* Wq = (const float*)d_in[2];
    const float* bq = (const float*)d_in[3];
    const float* Wk = (const float*)d_in[4];
    const float* bk = (const float*)d_in[5];
    const float* Wv = (const float*)d_in[6];
    const float* bv = (const float*)d_in[7];
    const float* Wd = (const float*)d_in[8];
    const float* bd = (const float*)d_in[9];
    const float* lw = (const float*)d_in[10];
    const float* lb = (const float*)d_in[11];
    float* out = (float*)d_out;

    float *pQ,*pK,*pV,*pctx,*ph;
    cudaGetSymbolAddress((void**)&pQ,  g_Q);
    cudaGetSymbolAddress((void**)&pK,  g_K);
    cudaGetSymbolAddress((void**)&pV,  g_V);
    cudaGetSymbolAddress((void**)&pctx,g_ctx);
    cudaGetSymbolAddress((void**)&ph,  g_hb);

    const int M = BB * LL;   // 16384

    init_h<<<1, LL>>>();
    init_T<<<LL, LL>>>();

    // fused QKV via tf32 tensor cores: z selects weight set
    qkv_mma<<<dim3(M/128, HIDC/64, 3), 256>>>(x, Wq, bq, pQ, Wk, bk, pK, Wv, bv, pV);

    // Gram matrices + diagonal sums -> R -> topk weights
    gram_mma<<<dim3(LL/128, LL/64, BB), 256>>>();
    diag_sum<<<BB, 256>>>();
    mc_topk<<<BB, 256>>>();

    // band filter via circulant GEMM (NN) for qs,ks,vs
    circ_mma<<<dim3(LL/128, HIDC/64, 3*BB), 256>>>();

    cudaFuncSetAttribute(attn_kernel, cudaFuncAttributeMaxDynamicSharedMemorySize,
                         4*64*65*sizeof(float));
    attn_kernel<<<dim3(LL/64, 1, BB*NHH), 256, 4*64*65*sizeof(float)>>>(mask);

    delay_agg<<<dim3(LL/8, BB), 256>>>();

    // output projection + residual via tf32 tensor cores
    outproj_mma<<<dim3(M/128, HIDC/64, 1), 256>>>(pctx, Wd, bd, x, ph);

    ln_kernel<<<M, 128>>>(ph, lw, lb, out);
}

// round 14
// speedup vs baseline: 1.6798x; 1.1064x over previous
#include <cuda_runtime.h>
#include <cstdint>
#include <math.h>

#define BB    32
#define LL    512
#define HIDC  512
#define NHH   8
#define EE    64
#define TOPK  62

// ---------------- device scratch (zero-initialized at module load) ----------------
__device__ float g_Q [BB*LL*HIDC];
__device__ float g_K [BB*LL*HIDC];
__device__ float g_V [BB*LL*HIDC];
__device__ float g_qs[BB*LL*HIDC];
__device__ float g_ks[BB*LL*HIDC];
__device__ float g_vs[BB*LL*HIDC];
__device__ float g_ctx[BB*LL*HIDC];
__device__ float g_hb [BB*LL*HIDC];
__device__ float g_G [BB*LL*LL];
__device__ float g_R [BB*LL];
__device__ float g_h [LL];
__device__ float g_T [LL*LL];
__device__ float g_wk[BB*TOPK];
__device__ int   g_dk[BB*TOPK];

// ---------------- trig/filter tables ----------------
__global__ void init_h() {
    int m = threadIdx.x;
    float acc = 0.f;
    for (int f = 102; f < 256; f++) {
        int ph = (f * m) & (LL - 1);
        acc += 2.0f * cospif((float)ph * (1.0f / 256.0f));
    }
    {
        int ph = (256 * m) & (LL - 1);
        acc += cospif((float)ph * (1.0f / 256.0f));
    }
    g_h[m] = acc * (1.0f / 512.0f);
}

__global__ void init_T() {
    int t = blockIdx.x, l = threadIdx.x;
    g_T[t * LL + l] = g_h[(t - l) & (LL - 1)];
}

// ---------------- tf32 helpers ----------------
__device__ __forceinline__ unsigned int to_tf32(float x) {
    unsigned int u;
    asm("cvt.rna.tf32.f32 %0, %1;" : "=r"(u) : "f"(x));
    return u;
}

__device__ __forceinline__ void mma_tf32(float* d, const uint4& a, const uint2& b) {
    asm volatile(
        "mma.sync.aligned.m16n8k8.row.col.f32.tf32.tf32.f32 "
        "{%0,%1,%2,%3}, {%4,%5,%6,%7}, {%8,%9}, {%0,%1,%2,%3};\n"
        : "+f"(d[0]), "+f"(d[1]), "+f"(d[2]), "+f"(d[3])
        : "r"(a.x), "r"(a.y), "r"(a.z), "r"(a.w), "r"(b.x), "r"(b.y));
}

// ---------------- tf32 tensor-core GEMM body (128x64 tile) ----------------
template<int RES, int BNN, int BIASF>
__device__ __forceinline__ void mma_gemm_body(
    const float* __restrict__ A, const float* __restrict__ B,
    const float* __restrict__ bias, const float* __restrict__ Rres,
    float* __restrict__ C)
{
    __shared__ unsigned int As2[2048];
    __shared__ unsigned int Bs2[1024];
    int tid = threadIdx.x, lane = tid & 31, wid = tid >> 5;
    int wm = wid >> 1, wn = wid & 1;
    int bm = blockIdx.x * 128, bn = blockIdx.y * 64;

    float acc[2][4][4];
    #pragma unroll
    for (int mi = 0; mi < 2; mi++)
        #pragma unroll
        for (int ni = 0; ni < 4; ni++)
            #pragma unroll
            for (int j = 0; j < 4; j++) acc[mi][ni][j] = 0.f;

    for (int k0 = 0; k0 < 512; k0 += 16) {
        #pragma unroll
        for (int q = 0; q < 2; q++) {
            int v = tid + q * 256;
            int r = v >> 2, c0 = (v & 3) * 4;
            float4 av = *(const float4*)&A[(size_t)(bm + r) * 512 + k0 + c0];
            int mt = r >> 4;
            int ks = c0 >> 3;
            int s  = ((r >> 3) & 1) + ((c0 & 4) ? 2 : 0);
            unsigned int* dst = &As2[((((mt*2 + ks)*32) + ((r & 7) << 2)) << 2) + s];
            dst[0]  = to_tf32(av.x);
            dst[4]  = to_tf32(av.y);
            dst[8]  = to_tf32(av.z);
            dst[12] = to_tf32(av.w);
        }
        if (BNN == 0) {
            int v = tid;
            int n = v >> 2, c0 = (v & 3) * 4;
            float4 bv = *(const float4*)&B[(size_t)(bn + n) * 512 + k0 + c0];
            int nt = n >> 3, ks = c0 >> 3;
            int s  = (c0 & 4) ? 1 : 0;
            unsigned int* dst = &Bs2[((((nt*2 + ks)*32) + ((n & 7) << 2)) << 1) + s];
            dst[0] = to_tf32(bv.x);
            dst[2] = to_tf32(bv.y);
            dst[4] = to_tf32(bv.z);
            dst[6] = to_tf32(bv.w);
        } else {
            int v = tid;
            int kr = v >> 4, c0 = (v & 15) * 4;
            float4 bv = *(const float4*)&B[(size_t)(k0 + kr) * 512 + bn + c0];
            int kk = kr & 7, ks = kr >> 3;
            int s  = (kk >> 2) & 1;
            int l0 = ((c0 & 7) << 2) | (kk & 3);
            int nt = c0 >> 3;
            unsigned int* dst = &Bs2[((((nt*2 + ks)*32) + l0) << 1) + s];
            dst[0]  = to_tf32(bv.x);
            dst[8]  = to_tf32(bv.y);
            dst[16] = to_tf32(bv.z);
            dst[24] = to_tf32(bv.w);
        }
        __syncthreads();
        #pragma unroll
        for (int ks = 0; ks < 2; ks++) {
            uint4 af[2];
            uint2 bf[4];
            #pragma unroll
            for (int mi = 0; mi < 2; mi++)
                af[mi] = *(const uint4*)&As2[((((wm*2 + mi)*2 + ks)*32) + lane) << 2];
            #pragma unroll
            for (int ni = 0; ni < 4; ni++)
                bf[ni] = *(const uint2*)&Bs2[((((wn*4 + ni)*2 + ks)*32) + lane) << 1];
            #pragma unroll
            for (int mi = 0; mi < 2; mi++)
                #pragma unroll
                for (int ni = 0; ni < 4; ni++)
                    mma_tf32(acc[mi][ni], af[mi], bf[ni]);
        }
        __syncthreads();
    }

    int r0 = bm + wm*32 + (lane >> 2);
    int cb = bn + wn*32 + 2*(lane & 3);
    #pragma unroll
    for (int mi = 0; mi < 2; mi++) {
        int ra = r0 + mi*16;
        int rb = ra + 8;
        #pragma unroll
        for (int ni = 0; ni < 4; ni++) {
            int col = cb + ni*8;
            float b0 = 0.f, b1 = 0.f;
            if (BIASF) { b0 = bias[col]; b1 = bias[col+1]; }
            float2 va, vb;
            va.x = acc[mi][ni][0] + b0; va.y = acc[mi][ni][1] + b1;
            vb.x = acc[mi][ni][2] + b0; vb.y = acc[mi][ni][3] + b1;
            if (RES) {
                va.x += Rres[(size_t)ra*512 + col];   va.y += Rres[(size_t)ra*512 + col+1];
                vb.x += Rres[(size_t)rb*512 + col];   vb.y += Rres[(size_t)rb*512 + col+1];
            }
            *(float2*)&C[(size_t)ra*512 + col] = va;
            *(float2*)&C[(size_t)rb*512 + col] = vb;
        }
    }
}

// ---------------- GEMM kernel instantiations ----------------
__global__ __launch_bounds__(256)
void qkv_mma(const float* __restrict__ A,
             const float* __restrict__ B0, const float* __restrict__ b0, float* __restrict__ C0,
             const float* __restrict__ B1, const float* __restrict__ b1, float* __restrict__ C1,
             const float* __restrict__ B2, const float* __restrict__ b2, float* __restrict__ C2)
{
    const float* Bw; const float* bias; float* C;
    if (blockIdx.z == 0)      { Bw = B0; bias = b0; C = C0; }
    else if (blockIdx.z == 1) { Bw = B1; bias = b1; C = C1; }
    else                      { Bw = B2; bias = b2; C = C2; }
    mma_gemm_body<0,0,1>(A, Bw, bias, nullptr, C);
}

__global__ __launch_bounds__(256)
void gram_mma()
{
    int b = blockIdx.z;
    mma_gemm_body<0,0,0>(g_Q + (size_t)b*LL*HIDC, g_K + (size_t)b*LL*HIDC,
                         nullptr, nullptr, g_G + (size_t)b*LL*LL);
}

__global__ __launch_bounds__(256)
void circ_mma()
{
    int bz = blockIdx.z;
    int b  = bz & (BB - 1);
    int wsel = bz >> 5;
    const float* X; float* Out;
    if (wsel == 0)      { X = g_Q; Out = g_qs; }
    else if (wsel == 1) { X = g_K; Out = g_ks; }
    else                { X = g_V; Out = g_vs; }
    mma_gemm_body<0,1,0>(g_T, X + (size_t)b*LL*HIDC, nullptr, nullptr,
                         Out + (size_t)b*LL*HIDC);
}

__global__ __launch_bounds__(256)
void outproj_mma(const float* __restrict__ A, const float* __restrict__ Bw,
                 const float* __restrict__ bias, const float* __restrict__ Rres,
                 float* __restrict__ C)
{
    mma_gemm_body<1,0,1>(A, Bw, bias, Rres, C);
}

// ---------------- diagonal sums (coalesced via smem staging) ----------------
__global__ __launch_bounds__(256)
void diag_sum()
{
    __shared__ float tile[16*LL];
    int b = blockIdx.x, tid = threadIdx.x;
    const float* Gb = g_G + (size_t)b*LL*LL;
    float r0 = 0.f, r1 = 0.f;
    for (int t0 = 0; t0 < LL; t0 += 16) {
        for (int i = tid; i < 16*LL/4; i += 256) {
            int row = i >> 7, c = (i & 127) * 4;
            *(float4*)&tile[row*LL + c] = *(const float4*)&Gb[(size_t)(t0 + row)*LL + c];
        }
        __syncthreads();
        #pragma unroll
        for (int l = 0; l < 16; l++) {
            int Lr = t0 + l;
            r0 += tile[l*LL + ((Lr - tid) & (LL - 1))];
            r1 += tile[l*LL + ((Lr - tid - 256) & (LL - 1))];
        }
        __syncthreads();
    }
    g_R[b*LL + tid]       = r0;
    g_R[b*LL + tid + 256] = r1;
}

// ---------------- mean-corr + top-k + softmax (one block/b) ----------------
__global__ __launch_bounds__(256)
void mc_topk()
{
    int b = blockIdx.x, tid = threadIdx.x;
    __shared__ float Rs[LL], hs[LL];
    __shared__ float mc[LL];
    __shared__ float bv[256]; __shared__ int bi[256];
    __shared__ float wk[TOPK]; __shared__ int dk[TOPK];
    __shared__ float ev[TOPK]; __shared__ float ssum;

    for (int i = tid; i < LL; i += 256) { Rs[i] = g_R[b*LL + i]; hs[i] = g_h[i]; }
    __syncthreads();

    const float sc = 1.0f / 512.0f;
    for (int t = tid; t < LL; t += 256) {
        float acc = 0.f;
        for (int d = 0; d < LL; d++)
            acc += Rs[d] * hs[(t - d) & (LL - 1)];
        mc[t] = acc * sc;
    }
    __syncthreads();

    for (int k = 0; k < TOPK; k++) {
        float v1 = mc[tid], v2 = mc[tid + 256];
        float vv; int ii;
        if (v2 > v1) { vv = v2; ii = tid + 256; } else { vv = v1; ii = tid; }
        bv[tid] = vv; bi[tid] = ii;
        __syncthreads();
        for (int s = 128; s > 0; s >>= 1) {
            if (tid < s) {
                float ov = bv[tid + s]; int oi = bi[tid + s];
                if (ov > bv[tid] || (ov == bv[tid] && oi < bi[tid])) { bv[tid] = ov; bi[tid] = oi; }
            }
            __syncthreads();
        }
        if (tid == 0) { wk[k] = bv[0]; dk[k] = bi[0]; mc[bi[0]] = -INFINITY; }
        __syncthreads();
    }
    if (tid < TOPK) ev[tid] = expf(wk[tid] - wk[0]);
    __syncthreads();
    if (tid == 0) { float s = 0.f; for (int k = 0; k < TOPK; k++) s += ev[k]; ssum = s; }
    __syncthreads();
    if (tid < TOPK) { g_wk[b*TOPK + tid] = ev[tid] / ssum; g_dk[b*TOPK + tid] = dk[tid]; }
}

// ---------------- flash attention via tf32 MMA; writes 0.5*ctx_sp ----------------
// Block: 64 q-rows of one (b,h); 256 threads = 8 warps (4 m x 2 n).
__global__ __launch_bounds__(256)
void attn_mma(const float* __restrict__ mask)
{
    extern __shared__ unsigned int smu[];
    unsigned int* Qf = smu;            // [4 mt][8 ks][32][4]
    unsigned int* Bk = smu + 4096;     // [8 nt][8 ks][32][2]
    unsigned int* Bv = smu + 8192;     // [8 nt][8 ks][32][2]
    unsigned int* Pf = smu + 12288;    // [4 mt][8 ks][32][4]
    __shared__ float rm[64], rl[64], rf[64];
    __shared__ float redm[2][64], reds[2][64];

    int bh = blockIdx.z, b = bh >> 3, h = bh & 7;
    int l0 = blockIdx.x * 64;
    int tid = threadIdx.x, lane = tid & 31, wid = tid >> 5;
    int wm = wid >> 1, wn = wid & 1;
    int row_a = wm*16 + (lane >> 2);
    int row_b = row_a + 8;

    // stage Q tile 64x64 -> A-frag layout (once)
    #pragma unroll
    for (int it = 0; it < 4; it++) {
        int v = tid + it*256;
        int r = v >> 4, c0 = (v & 15) * 4;
        float4 qv = *(const float4*)&g_qs[((size_t)b*LL + l0 + r)*HIDC + h*EE + c0];
        int mt = r >> 4, s = ((r>>3)&1) + ((c0&4)?2:0);
        unsigned int* dst = &Qf[(((mt*8 + (c0>>3))*32) + ((r&7)<<2))*4 + s];
        dst[0]=to_tf32(qv.x); dst[4]=to_tf32(qv.y); dst[8]=to_tf32(qv.z); dst[12]=to_tf32(qv.w);
    }
    if (tid < 64) { rm[tid] = -INFINITY; rl[tid] = 0.f; }
    float oacc[4][4] = {};
    __syncthreads();

    for (int m0 = 0; m0 < LL; m0 += 64) {
        // stage K (NT B-frags) and V (NN B-frags)
        #pragma unroll
        for (int it = 0; it < 4; it++) {
            int v = tid + it*256;
            int j = v >> 4, c0 = (v & 15) * 4;
            size_t base = ((size_t)b*LL + m0 + j)*HIDC + h*EE + c0;
            float4 kv = *(const float4*)&g_ks[base];
            {
                int nt = j >> 3, s = (c0&4)?1:0;
                unsigned int* dst = &Bk[(((nt*8 + (c0>>3))*32) + ((j&7)<<2))*2 + s];
                dst[0]=to_tf32(kv.x); dst[2]=to_tf32(kv.y); dst[4]=to_tf32(kv.z); dst[6]=to_tf32(kv.w);
            }
            float4 vv = *(const float4*)&g_vs[base];
            {
                int kk = j & 7, ks2 = j >> 3, s = (kk>>2)&1;
                int lb = ((c0&7)<<2) | (kk&3);
                int nt = c0 >> 3;
                unsigned int* dst = &Bv[(((nt*8 + ks2)*32) + lb)*2 + s];
                dst[0]=to_tf32(vv.x); dst[8]=to_tf32(vv.y); dst[16]=to_tf32(vv.z); dst[24]=to_tf32(vv.w);
            }
        }
        __syncthreads();

        // S = Q K^T  (warp tile 16x32)
        float s4[4][4] = {};
        #pragma unroll
        for (int ks = 0; ks < 8; ks++) {
            uint4 af = *(const uint4*)&Qf[(((wm*8+ks)*32) + lane)*4];
            #pragma unroll
            for (int ni = 0; ni < 4; ni++) {
                uint2 bf = *(const uint2*)&Bk[((((wn*4+ni)*8+ks)*32) + lane)*2];
                mma_tf32(s4[ni], af, bf);
            }
        }
        // scale + mask
        #pragma unroll
        for (int ni = 0; ni < 4; ni++) {
            int col = wn*32 + ni*8 + 2*(lane&3);
            float2 ma = *(const float2*)&mask[((size_t)b*LL + l0 + row_a)*LL + m0 + col];
            float2 mb = *(const float2*)&mask[((size_t)b*LL + l0 + row_b)*LL + m0 + col];
            s4[ni][0] = s4[ni][0]*0.125f + ma.x;
            s4[ni][1] = s4[ni][1]*0.125f + ma.y;
            s4[ni][2] = s4[ni][2]*0.125f + mb.x;
            s4[ni][3] = s4[ni][3]*0.125f + mb.y;
        }
        // row max (warp, then cross-warp)
        float mxa = -INFINITY, mxb = -INFINITY;
        #pragma unroll
        for (int ni = 0; ni < 4; ni++) {
            mxa = fmaxf(mxa, fmaxf(s4[ni][0], s4[ni][1]));
            mxb = fmaxf(mxb, fmaxf(s4[ni][2], s4[ni][3]));
        }
        #pragma unroll
        for (int o = 1; o < 4; o <<= 1) {
            mxa = fmaxf(mxa, __shfl_xor_sync(0xffffffffu, mxa, o));
            mxb = fmaxf(mxb, __shfl_xor_sync(0xffffffffu, mxb, o));
        }
        if ((lane & 3) == 0) { redm[wn][row_a] = mxa; redm[wn][row_b] = mxb; }
        __syncthreads();
        if (wn == 0 && (lane & 3) == 0) {
            #pragma unroll
            for (int rr = 0; rr < 2; rr++) {
                int r = rr ? row_b : row_a;
                float t = fmaxf(redm[0][r], redm[1][r]);
                float mo = rm[r];
                float mn = fmaxf(mo, t);
                rf[r] = expf(mo - mn);
                rm[r] = mn;
            }
        }
        __syncthreads();
        // p = exp(s - m), partial sums, stage P as A-frags
        float ra = rm[row_a], rb = rm[row_b];
        float sa = 0.f, sb = 0.f;
        #pragma unroll
        for (int ni = 0; ni < 4; ni++) {
            float p0 = expf(s4[ni][0] - ra), p1 = expf(s4[ni][1] - ra);
            float p2 = expf(s4[ni][2] - rb), p3 = expf(s4[ni][3] - rb);
            sa += p0 + p1; sb += p2 + p3;
            int j0 = wn*32 + ni*8 + 2*(lane&3);
            int ksj = j0 >> 3;
            int la0 = ((row_a&7)<<2) | (j0&3);
            int la1 = ((row_a&7)<<2) | ((j0+1)&3);
            int sl0 = (j0&4) ? 2 : 0;
            unsigned int* base = &Pf[((wm*8 + ksj)*32)*4];
            base[la0*4 + sl0]     = to_tf32(p0);
            base[la1*4 + sl0]     = to_tf32(p1);
            base[la0*4 + sl0 + 1] = to_tf32(p2);
            base[la1*4 + sl0 + 1] = to_tf32(p3);
        }
        #pragma unroll
        for (int o = 1; o < 4; o <<= 1) {
            sa += __shfl_xor_sync(0xffffffffu, sa, o);
            sb += __shfl_xor_sync(0xffffffffu, sb, o);
        }
        if ((lane & 3) == 0) { reds[wn][row_a] = sa; reds[wn][row_b] = sb; }
        __syncthreads();
        if (wn == 0 && (lane & 3) == 0) {
            #pragma unroll
            for (int rr = 0; rr < 2; rr++) {
                int r = rr ? row_b : row_a;
                rl[r] = rl[r]*rf[r] + reds[0][r] + reds[1][r];
            }
        }
        // rescale O accumulators and accumulate P·V
        float fa = rf[row_a], fb = rf[row_b];
        #pragma unroll
        for (int ni = 0; ni < 4; ni++) {
            oacc[ni][0] *= fa; oacc[ni][1] *= fa;
            oacc[ni][2] *= fb; oacc[ni][3] *= fb;
        }
        #pragma unroll
        for (int ks = 0; ks < 8; ks++) {
            uint4 af = *(const uint4*)&Pf[(((wm*8+ks)*32) + lane)*4];
            #pragma unroll
            for (int ni = 0; ni < 4; ni++) {
                uint2 bf = *(const uint2*)&Bv[((((wn*4+ni)*8+ks)*32) + lane)*2];
                mma_tf32(oacc[ni], af, bf);
            }
        }
        __syncthreads();
    }

    float inva = 0.5f / rl[row_a];
    float invb = 0.5f / rl[row_b];
    #pragma unroll
    for (int ni = 0; ni < 4; ni++) {
        int col = wn*32 + ni*8 + 2*(lane&3);
        float2 oa, ob;
        oa.x = oacc[ni][0]*inva; oa.y = oacc[ni][1]*inva;
        ob.x = oacc[ni][2]*invb; ob.y = oacc[ni][3]*invb;
        *(float2*)&g_ctx[((size_t)b*LL + l0 + row_a)*HIDC + h*EE + col] = oa;
        *(float2*)&g_ctx[((size_t)b*LL + l0 + row_b)*HIDC + h*EE + col] = ob;
    }
}

// ---------------- time-delay aggregation ----------------
__global__ __launch_bounds__(256)
void delay_agg()
{
    __shared__ float ws[TOPK]; __shared__ int ds[TOPK];
    int l0 = blockIdx.x * 8, b = blockIdx.y, tid = threadIdx.x;
    if (tid < TOPK) { ws[tid] = g_wk[b*TOPK + tid]; ds[tid] = g_dk[b*TOPK + tid]; }
    __syncthreads();
    int c2 = tid;
    const float2* Vb = (const float2*)(g_V + (size_t)b*LL*HIDC);
    float2 acc[8];
    #pragma unroll
    for (int i = 0; i < 8; i++) acc[i] = make_float2(0.f, 0.f);
    for (int k = 0; k < TOPK; k++) {
        float w = ws[k]; int d = ds[k];
        #pragma unroll
        for (int i = 0; i < 8; i++) {
            int pos = (l0 + i + d) & (LL - 1);
            float2 v = Vb[(size_t)pos*(HIDC/2) + c2];
            acc[i].x += w*v.x; acc[i].y += w*v.y;
        }
    }
    #pragma unroll
    for (int i = 0; i < 8; i++) {
        size_t off = ((size_t)b*LL + l0 + i)*(HIDC/2) + c2;
        float2* C = (float2*)g_ctx;
        float2 cur = C[off];
        cur.x += 0.5f*acc[i].x; cur.y += 0.5f*acc[i].y;
        C[off] = cur;
    }
}

// ---------------- layernorm ----------------
__global__ __launch_bounds__(128)
void ln_kernel(const float* __restrict__ hb, const float* __restrict__ w,
               const float* __restrict__ bp, float* __restrict__ out)
{
    int row = blockIdx.x, tid = threadIdx.x;
    const float* hr = hb + (size_t)row*HIDC;
    float4 xv = *(const float4*)&hr[tid*4];
    float s  = xv.x + xv.y + xv.z + xv.w;
    float ss = xv.x*xv.x + xv.y*xv.y + xv.z*xv.z + xv.w*xv.w;
    #pragma unroll
    for (int o = 16; o; o >>= 1) {
        s  += __shfl_xor_sync(0xffffffffu, s,  o);
        ss += __shfl_xor_sync(0xffffffffu, ss, o);
    }
    __shared__ float s1[4], s2s[4];
    int wp = tid >> 5;
    if ((tid & 31) == 0) { s1[wp] = s; s2s[wp] = ss; }
    __syncthreads();
    float st  = s1[0] + s1[1] + s1[2] + s1[3];
    float sst = s2s[0] + s2s[1] + s2s[2] + s2s[3];
    float mean = st * (1.0f / HIDC);
    float var  = fmaxf(sst * (1.0f / HIDC) - mean*mean, 0.0f);
    float inv  = rsqrtf(var + 1e-12f);
    int c = tid * 4;
    float4 o4;
    o4.x = w[c+0]*((xv.x - mean)*inv) + bp[c+0];
    o4.y = w[c+1]*((xv.y - mean)*inv) + bp[c+1];
    o4.z = w[c+2]*((xv.z - mean)*inv) + bp[c+2];
    o4.w = w[c+3]*((xv.w - mean)*inv) + bp[c+3];
    *(float4*)&out[(size_t)row*HIDC + c] = o4;
}

// ---------------- launch ----------------
extern "C" void kernel_launch(void* const* d_in, const int* in_sizes, int n_in,
                              void* d_out, int out_size)
{
    const float* x    = (const float*)d_in[0];
    const float* mask = (const float*)d_in[1];
    const float* Wq = (const float*)d_in[2];
    const float* bq = (const float*)d_in[3];
    const float* Wk = (const float*)d_in[4];
    const float* bk = (const float*)d_in[5];
    const float* Wv = (const float*)d_in[6];
    const float* bv = (const float*)d_in[7];
    const float* Wd = (const float*)d_in[8];
    const float* bd = (const float*)d_in[9];
    const float* lw = (const float*)d_in[10];
    const float* lb = (const float*)d_in[11];
    float* out = (float*)d_out;

    float *pQ,*pK,*pV,*pctx,*ph;
    cudaGetSymbolAddress((void**)&pQ,  g_Q);
    cudaGetSymbolAddress((void**)&pK,  g_K);
    cudaGetSymbolAddress((void**)&pV,  g_V);
    cudaGetSymbolAddress((void**)&pctx,g_ctx);
    cudaGetSymbolAddress((void**)&ph,  g_hb);

    const int M = BB * LL;   // 16384

    init_h<<<1, LL>>>();
    init_T<<<LL, LL>>>();

    qkv_mma<<<dim3(M/128, HIDC/64, 3), 256>>>(x, Wq, bq, pQ, Wk, bk, pK, Wv, bv, pV);

    gram_mma<<<dim3(LL/128, LL/64, BB), 256>>>();
    diag_sum<<<BB, 256>>>();
    mc_topk<<<BB, 256>>>();

    circ_mma<<<dim3(LL/128, HIDC/64, 3*BB), 256>>>();

    cudaFuncSetAttribute(attn_mma, cudaFuncAttributeMaxDynamicSharedMemorySize, 65536);
    attn_mma<<<dim3(LL/64, 1, BB*NHH), 256, 65536>>>(mask);

    delay_agg<<<dim3(LL/8, BB), 256>>>();

    outproj_mma<<<dim3(M/128, HIDC/64, 1), 256>>>(pctx, Wd, bd, x, ph);

    ln_kernel<<<M, 128>>>(ph, lw, lb, out);
}